// round 3
// baseline (speedup 1.0000x reference)
#include <cuda_runtime.h>
#include <cuda_bf16.h>
#include <math.h>
#include <stdint.h>

// Problem dims
#define BB 512
#define IN_DIM 1024
#define HH 512
#define EE 512
#define VV 2048
#define LL 32

// JAX threefry mode: 1 = partitionable (default in jax >= 0.4.36), 0 = original
#define JAX_PARTITIONABLE 1

// Output layout (floats): seq [512,33], probs [512,33,2048], logp [512,33], ent [512,33]
#define SEQ_OFF   ((size_t)0)
#define PROB_OFF  ((size_t)(BB * (LL + 1)))
#define LOGP_OFF  (PROB_OFF + (size_t)BB * (LL + 1) * VV)
#define ENT_OFF   (LOGP_OFF + (size_t)BB * (LL + 1))

// Scratch (device globals; no allocation allowed)
__device__ float g_h[BB * HH];
__device__ float g_c[BB * HH];
__device__ float g_e[BB * EE];
__device__ float g_gates[BB * 4 * HH];
__device__ float g_logits[BB * VV];

// ---------------------------------------------------------------------------
// Threefry2x32 (20 rounds) — device + host identical
// ---------------------------------------------------------------------------
__host__ __device__ __forceinline__ void threefry2x32(
    unsigned k0, unsigned k1, unsigned x0, unsigned x1,
    unsigned& o0, unsigned& o1)
{
    unsigned k2 = k0 ^ k1 ^ 0x1BD11BDAu;
    x0 += k0; x1 += k1;
#define TF_RND(r) { x0 += x1; x1 = (x1 << (r)) | (x1 >> (32 - (r))); x1 ^= x0; }
    TF_RND(13) TF_RND(15) TF_RND(26) TF_RND(6)   x0 += k1; x1 += k2 + 1u;
    TF_RND(17) TF_RND(29) TF_RND(16) TF_RND(24)  x0 += k2; x1 += k0 + 2u;
    TF_RND(13) TF_RND(15) TF_RND(26) TF_RND(6)   x0 += k0; x1 += k1 + 3u;
    TF_RND(17) TF_RND(29) TF_RND(16) TF_RND(24)  x0 += k1; x1 += k2 + 4u;
    TF_RND(13) TF_RND(15) TF_RND(26) TF_RND(6)   x0 += k2; x1 += k0 + 5u;
#undef TF_RND
    o0 = x0; o1 = x1;
}

// ---------------------------------------------------------------------------
// Generic 2-source SGEMM: C[M,N] = A0@W0 + A1@W1 + bias0 + bias1
// A row-major [M,K] (ld=K), W row-major [K,N] (ld=N). M%64==0, N%128==0, K%16==0.
// ---------------------------------------------------------------------------
__global__ void __launch_bounds__(256)
gemm2_kernel(const float* __restrict__ A0, const float* __restrict__ W0, int K0,
             const float* __restrict__ A1, const float* __restrict__ W1, int K1,
             const float* __restrict__ bias0, const float* __restrict__ bias1,
             float* __restrict__ C, int N)
{
    const int BM = 64, BN = 128, BK = 16;
    __shared__ __align__(16) float As[16][64];
    __shared__ __align__(16) float Bs[16][128];

    int tid = threadIdx.x;
    int tx = tid & 15;        // 0..15 -> cols (x8)
    int ty = tid >> 4;        // 0..15 -> rows (x4)
    int bm = blockIdx.y * BM;
    int bn = blockIdx.x * BN;

    float acc[4][8];
#pragma unroll
    for (int i = 0; i < 4; i++)
#pragma unroll
        for (int j = 0; j < 8; j++) acc[i][j] = 0.f;

    int arow = tid >> 2;            // 0..63
    int acol = (tid & 3) << 2;      // 0,4,8,12
    int brow = tid >> 5;            // 0..7
    int bcol = (tid & 31) << 2;     // 0..124

    for (int s = 0; s < 2; s++) {
        const float* A = (s == 0) ? A0 : A1;
        const float* W = (s == 0) ? W0 : W1;
        int K = (s == 0) ? K0 : K1;
        if (A == nullptr) continue;
        const float* Ab = A + (size_t)bm * K;
        for (int k0 = 0; k0 < K; k0 += BK) {
            float4 av = *(const float4*)(Ab + (size_t)arow * K + k0 + acol);
            As[acol + 0][arow] = av.x;
            As[acol + 1][arow] = av.y;
            As[acol + 2][arow] = av.z;
            As[acol + 3][arow] = av.w;
            const float* Wb = W + (size_t)k0 * N + bn;
            *(float4*)&Bs[brow][bcol]     = *(const float4*)(Wb + (size_t)brow * N + bcol);
            *(float4*)&Bs[brow + 8][bcol] = *(const float4*)(Wb + (size_t)(brow + 8) * N + bcol);
            __syncthreads();
#pragma unroll
            for (int kk = 0; kk < BK; kk++) {
                float a[4], b[8];
                *(float4*)a       = *(const float4*)&As[kk][ty * 4];
                *(float4*)b       = *(const float4*)&Bs[kk][tx * 8];
                *(float4*)(b + 4) = *(const float4*)&Bs[kk][tx * 8 + 4];
#pragma unroll
                for (int i = 0; i < 4; i++)
#pragma unroll
                    for (int j = 0; j < 8; j++)
                        acc[i][j] = fmaf(a[i], b[j], acc[i][j]);
            }
            __syncthreads();
        }
    }

#pragma unroll
    for (int i = 0; i < 4; i++) {
        float* Crow = C + (size_t)(bm + ty * 4 + i) * N + bn + tx * 8;
#pragma unroll
        for (int j = 0; j < 8; j++) {
            int col = bn + tx * 8 + j;
            float bv = 0.f;
            if (bias0) bv += bias0[col];
            if (bias1) bv += bias1[col];
            Crow[j] = acc[i][j] + bv;
        }
    }
}

// ---------------------------------------------------------------------------
// Init: c0 = 0, e0 = broadcast(sos)
// ---------------------------------------------------------------------------
__global__ void __launch_bounds__(256)
init_kernel(const float* __restrict__ sos)
{
    int idx = blockIdx.x * blockDim.x + threadIdx.x;
    if (idx < BB * HH) {
        g_c[idx] = 0.f;
        g_e[idx] = sos[idx & (EE - 1)];
    }
}

// ---------------------------------------------------------------------------
// LSTM cell: gates [B,4H] (i,f,g,o) -> h,c
// ---------------------------------------------------------------------------
__device__ __forceinline__ float sigmoidf_(float x) { return 1.f / (1.f + expf(-x)); }

__global__ void __launch_bounds__(256)
cell_kernel()
{
    int idx = blockIdx.x * blockDim.x + threadIdx.x;
    if (idx >= BB * HH) return;
    int b = idx >> 9;           // /512
    int j = idx & 511;
    const float* gr = g_gates + (size_t)b * (4 * HH);
    float ig = gr[j];
    float fg = gr[HH + j];
    float gg = gr[2 * HH + j];
    float og = gr[3 * HH + j];
    float c = g_c[idx];
    float cn = sigmoidf_(fg) * c + sigmoidf_(ig) * tanhf(gg);
    float hn = sigmoidf_(og) * tanhf(cn);
    g_c[idx] = cn;
    g_h[idx] = hn;
}

// ---------------------------------------------------------------------------
// Per-row: log_softmax, probs, entropy, Gumbel-argmax sample, embed gather
// ---------------------------------------------------------------------------
__device__ __forceinline__ float neg_log_u(unsigned bits)
{
    // u = bitcast(0x3f800000 | bits>>9) - 1  in [0,1);  returns -log(u)
    float f = __uint_as_float(0x3f800000u | (bits >> 9));
    float u = f - 1.0f;
    if (u > 0.9f) {
        // d = 1-u computed exactly; series for -log(1-d), rel err ~1e-8 (fast-math safe)
        float d = 2.0f - f;
        return d * (1.0f + d * (0.5f + d * (0.333333343f + d * (0.25f +
               d * (0.2f + d * (0.166666672f + d * 0.142857149f))))));
    }
    if (u == 0.0f) u = 1.17549435e-38f;
    return -logf(u);
}

__global__ void __launch_bounds__(256)
sample_kernel(const float* __restrict__ embedding,
              float* __restrict__ out, int t,
              unsigned sk0, unsigned sk1)
{
    const int T = 256;
    int b = blockIdx.x;
    int tid = threadIdx.x;
    __shared__ float s_row[VV];
    __shared__ float s_red[T];
    __shared__ int   s_idx[T];
    __shared__ float s_shift;
    __shared__ float s_ent;
    __shared__ int   s_sym;

    const float* row = g_logits + (size_t)b * VV;
    const float NEG_INF = __int_as_float(0xff800000);

    // pass 1: load + max
    float m = NEG_INF;
    for (int v = tid; v < VV; v += T) {
        float x = row[v];
        s_row[v] = x;
        m = fmaxf(m, x);
    }
    s_red[tid] = m;
    __syncthreads();
    for (int o = T / 2; o > 0; o >>= 1) {
        if (tid < o) s_red[tid] = fmaxf(s_red[tid], s_red[tid + o]);
        __syncthreads();
    }
    m = s_red[0];
    __syncthreads();

    // pass 2: sum exp
    float z = 0.f;
    for (int v = tid; v < VV; v += T) z += expf(s_row[v] - m);
    s_red[tid] = z;
    __syncthreads();
    for (int o = T / 2; o > 0; o >>= 1) {
        if (tid < o) s_red[tid] += s_red[tid + o];
        __syncthreads();
    }
    if (tid == 0) s_shift = m + logf(s_red[0]);
    __syncthreads();
    float shift = s_shift;

    // pass 3: probs + entropy + gumbel + per-thread argmax
    float entsum = 0.f;
    float best = NEG_INF;
    int bi = 0;
    size_t pbase = PROB_OFF + ((size_t)b * (LL + 1) + t) * VV;
    for (int v = tid; v < VV; v += T) {
        float lp = s_row[v] - shift;
        float p = expf(lp);
        entsum += p * lp;
        out[pbase + v] = p;
        unsigned r0, r1, bits;
#if JAX_PARTITIONABLE
        threefry2x32(sk0, sk1, 0u, (unsigned)(b * VV + v), r0, r1);
        bits = r0 ^ r1;
#else
        unsigned j0 = (unsigned)((b & 255) * VV + v);
        threefry2x32(sk0, sk1, j0, j0 + 524288u, r0, r1);
        bits = (b < 256) ? r0 : r1;
#endif
        float inner = neg_log_u(bits);
        float g = -logf(inner);
        float val = lp + g;
        if (val > best) { best = val; bi = v; }
    }

    // reduce entropy
    __syncthreads();
    s_red[tid] = entsum;
    __syncthreads();
    for (int o = T / 2; o > 0; o >>= 1) {
        if (tid < o) s_red[tid] += s_red[tid + o];
        __syncthreads();
    }
    if (tid == 0) s_ent = -s_red[0];
    __syncthreads();

    // reduce argmax (tie -> lower index, matching jnp.argmax)
    s_red[tid] = best;
    s_idx[tid] = bi;
    __syncthreads();
    for (int o = T / 2; o > 0; o >>= 1) {
        if (tid < o) {
            float v2 = s_red[tid + o];
            int i2 = s_idx[tid + o];
            if (v2 > s_red[tid] || (v2 == s_red[tid] && i2 < s_idx[tid])) {
                s_red[tid] = v2;
                s_idx[tid] = i2;
            }
        }
        __syncthreads();
    }
    if (tid == 0) {
        int sym = s_idx[0];
        s_sym = sym;
        size_t so = (size_t)b * (LL + 1) + t;
        out[SEQ_OFF + so] = (float)sym;
        out[LOGP_OFF + so] = s_row[sym] - shift;
        out[ENT_OFF + so] = s_ent;
    }
    __syncthreads();

    // gather next embedding
    int sym = s_sym;
    const float* emb = embedding + (size_t)sym * EE;
    float* er = g_e + (size_t)b * EE;
    for (int j = tid; j < EE; j += T) er[j] = emb[j];
}

// ---------------------------------------------------------------------------
// EOS step (t = 32): seq/logp/ent = 0, probs = 1
// ---------------------------------------------------------------------------
__global__ void __launch_bounds__(256)
eos_kernel(float* __restrict__ out)
{
    int idx = blockIdx.x * blockDim.x + threadIdx.x;
    if (idx < BB * VV) {
        int b = idx / VV;
        int v = idx % VV;
        out[PROB_OFF + ((size_t)b * (LL + 1) + LL) * VV + v] = 1.0f;
    }
    if (idx < BB) {
        size_t so = (size_t)idx * (LL + 1) + LL;
        out[SEQ_OFF + so] = 0.f;
        out[LOGP_OFF + so] = 0.f;
        out[ENT_OFF + so] = 0.f;
    }
}

// ---------------------------------------------------------------------------
// Host launcher
// ---------------------------------------------------------------------------
extern "C" void kernel_launch(void* const* d_in, const int* in_sizes, int n_in,
                              void* d_out, int out_size)
{
    const float* x         = (const float*)d_in[0];
    const float* agent_w   = (const float*)d_in[1];
    const float* agent_b   = (const float*)d_in[2];
    const float* sos       = (const float*)d_in[3];
    const float* embedding = (const float*)d_in[4];
    const float* w_ih      = (const float*)d_in[5];
    const float* w_hh      = (const float*)d_in[6];
    const float* b_ih      = (const float*)d_in[7];
    const float* b_hh      = (const float*)d_in[8];
    const float* out_w     = (const float*)d_in[9];
    const float* out_b     = (const float*)d_in[10];
    float* out = (float*)d_out;

    float *hp, *gp, *lp;
    cudaGetSymbolAddress((void**)&hp, g_h);
    cudaGetSymbolAddress((void**)&gp, g_gates);
    cudaGetSymbolAddress((void**)&lp, g_logits);
    float *ep;
    cudaGetSymbolAddress((void**)&ep, g_e);

    // init c0, e0
    init_kernel<<<(BB * HH + 255) / 256, 256>>>(sos);
    // h0 = x @ agent_w + agent_b   [512,512], K=1024
    gemm2_kernel<<<dim3(HH / 128, BB / 64), 256>>>(
        x, agent_w, IN_DIM, nullptr, nullptr, 0, agent_b, nullptr, hp, HH);

    // key chain: jax.random.key(1) -> (0, 1)
    unsigned k0 = 0u, k1 = 1u;
    for (int t = 0; t < LL; t++) {
        unsigned nk0, nk1, sk0, sk1;
#if JAX_PARTITIONABLE
        threefry2x32(k0, k1, 0u, 0u, nk0, nk1);   // key' = tf(key,(0,0))
        threefry2x32(k0, k1, 0u, 1u, sk0, sk1);   // sk   = tf(key,(0,1))
#else
        unsigned a0, a1, c0_, c1_;
        threefry2x32(k0, k1, 0u, 2u, a0, a1);
        threefry2x32(k0, k1, 1u, 3u, c0_, c1_);
        nk0 = a0; nk1 = c0_; sk0 = a1; sk1 = c1_;
#endif
        k0 = nk0; k1 = nk1;

        // gates = e @ w_ih + h @ w_hh + b_ih + b_hh   [512, 2048]
        gemm2_kernel<<<dim3((4 * HH) / 128, BB / 64), 256>>>(
            ep, w_ih, EE, hp, w_hh, HH, b_ih, b_hh, gp, 4 * HH);
        // LSTM cell
        cell_kernel<<<(BB * HH + 255) / 256, 256>>>();
        // logits = h @ out_w + out_b   [512, 2048]
        gemm2_kernel<<<dim3(VV / 128, BB / 64), 256>>>(
            hp, out_w, HH, nullptr, nullptr, 0, out_b, nullptr, lp, VV);
        // softmax + sample + outputs + next embedding
        sample_kernel<<<BB, 256>>>(embedding, out, t, sk0, sk1);
    }

    eos_kernel<<<(BB * VV + 255) / 256, 256>>>(out);
}

// round 4
// speedup vs baseline: 1.5710x; 1.5710x over previous
#include <cuda_runtime.h>
#include <cuda_bf16.h>
#include <math.h>
#include <stdint.h>

// Problem dims
#define BB 512
#define IN_DIM 1024
#define HH 512
#define EE 512
#define VV 2048
#define LL 32

// Output layout (floats): seq [512,33], probs [512,33,2048], logp [512,33], ent [512,33]
#define SEQ_OFF   ((size_t)0)
#define PROB_OFF  ((size_t)(BB * (LL + 1)))
#define LOGP_OFF  (PROB_OFF + (size_t)BB * (LL + 1) * VV)
#define ENT_OFF   (LOGP_OFF + (size_t)BB * (LL + 1))

// Scratch (device globals; no allocation allowed)
__device__ float g_h0[BB * HH];
__device__ float g_h1[BB * HH];
__device__ float g_c[BB * HH];
__device__ float g_logits[BB * VV];
__device__ float g_table[VV * 4 * HH];      // emb @ w_ih + b_ih + b_hh, permuted cols (16 MB)
__device__ float g_wih_perm[EE * 4 * HH];
__device__ float g_whh_perm[HH * 4 * HH];
__device__ float g_bias_perm[4 * HH];
__device__ float g_sosrow[4 * HH];          // sos @ w_ih + biases, permuted
__device__ int   g_sym[BB];

typedef unsigned long long ull;

// ---------------------------------------------------------------------------
// f32x2 helpers (sm_103a packed fp32 FMA)
// ---------------------------------------------------------------------------
__device__ __forceinline__ ull pk2(float x) {
    ull r; asm("mov.b64 %0,{%1,%1};" : "=l"(r) : "f"(x)); return r;
}
__device__ __forceinline__ void fma2(ull& d, ull a, ull b) {
    asm("fma.rn.f32x2 %0,%1,%2,%0;" : "+l"(d) : "l"(a), "l"(b));
}
__device__ __forceinline__ void up2(ull v, float& lo, float& hi) {
    asm("mov.b64 {%0,%1},%2;" : "=f"(lo), "=f"(hi) : "l"(v));
}

// ---------------------------------------------------------------------------
// Threefry2x32 (20 rounds) — device + host identical
// ---------------------------------------------------------------------------
__host__ __device__ __forceinline__ void threefry2x32(
    unsigned k0, unsigned k1, unsigned x0, unsigned x1,
    unsigned& o0, unsigned& o1)
{
    unsigned k2 = k0 ^ k1 ^ 0x1BD11BDAu;
    x0 += k0; x1 += k1;
#define TF_RND(r) { x0 += x1; x1 = (x1 << (r)) | (x1 >> (32 - (r))); x1 ^= x0; }
    TF_RND(13) TF_RND(15) TF_RND(26) TF_RND(6)   x0 += k1; x1 += k2 + 1u;
    TF_RND(17) TF_RND(29) TF_RND(16) TF_RND(24)  x0 += k2; x1 += k0 + 2u;
    TF_RND(13) TF_RND(15) TF_RND(26) TF_RND(6)   x0 += k0; x1 += k1 + 3u;
    TF_RND(17) TF_RND(29) TF_RND(16) TF_RND(24)  x0 += k1; x1 += k2 + 4u;
    TF_RND(13) TF_RND(15) TF_RND(26) TF_RND(6)   x0 += k2; x1 += k0 + 5u;
#undef TF_RND
    o0 = x0; o1 = x1;
}

__device__ __forceinline__ float sigmoidf_(float x) { return 1.f / (1.f + expf(-x)); }

// ---------------------------------------------------------------------------
// f32x2 SGEMM, BM=64 BN=128 BK=16, 256 threads, double-buffered, 1 sync/tile.
// C[M,N] = A[M,K] @ W[K,N]  (+bias)  (+rowtab[sym[r]] or broadcast rowtab)
// fuse=1: permuted-gate LSTM epilogue -> writes hout, updates g_c (no C write)
// ---------------------------------------------------------------------------
__global__ void __launch_bounds__(256)
gemm_f2(const float* __restrict__ A, const float* __restrict__ W,
        int K, int N,
        const float* __restrict__ bias,
        const float* __restrict__ rowtab, const int* __restrict__ sym,
        float* __restrict__ C, float* __restrict__ hout, int fuse)
{
    __shared__ __align__(16) float As[2][16][64];
    __shared__ __align__(16) float Bs[2][16][128];

    int tid = threadIdx.x;
    int tx = tid & 15;         // 0..15 -> col groups of 8
    int ty = tid >> 4;         // 0..15 -> row groups of 4
    int bm = blockIdx.y * 64;
    int bn = blockIdx.x * 128;

    ull acc[4][4];
#pragma unroll
    for (int i = 0; i < 4; i++)
#pragma unroll
        for (int j = 0; j < 4; j++) acc[i][j] = 0ull;

    int arow = tid >> 2;            // 0..63
    int acol = (tid & 3) << 2;      // 0,4,8,12
    int brow = tid >> 5;            // 0..7
    int bcol = (tid & 31) << 2;     // 0..124

    const float* Aptr = A + (size_t)(bm + arow) * K + acol;
    const float* Wptr = W + (size_t)brow * N + bn + bcol;
    int NT = K >> 4;

    // preload tile 0
    float4 pa  = *(const float4*)Aptr;
    float4 pb0 = *(const float4*)Wptr;
    float4 pb1 = *(const float4*)(Wptr + (size_t)8 * N);
    As[0][acol + 0][arow] = pa.x;
    As[0][acol + 1][arow] = pa.y;
    As[0][acol + 2][arow] = pa.z;
    As[0][acol + 3][arow] = pa.w;
    *(float4*)&Bs[0][brow][bcol]     = pb0;
    *(float4*)&Bs[0][brow + 8][bcol] = pb1;
    __syncthreads();

    for (int kt = 0; kt < NT; kt++) {
        int buf = kt & 1;
        if (kt + 1 < NT) {
            pa  = *(const float4*)(Aptr + (kt + 1) * 16);
            pb0 = *(const float4*)(Wptr + (size_t)(kt + 1) * 16 * N);
            pb1 = *(const float4*)(Wptr + (size_t)((kt + 1) * 16 + 8) * N);
        }
#pragma unroll
        for (int kk = 0; kk < 16; kk++) {
            float4 av = *(const float4*)&As[buf][kk][ty * 4];
            ulonglong2 b01 = *(const ulonglong2*)&Bs[buf][kk][tx * 8];
            ulonglong2 b23 = *(const ulonglong2*)&Bs[buf][kk][tx * 8 + 4];
            ull a0 = pk2(av.x), a1 = pk2(av.y), a2 = pk2(av.z), a3 = pk2(av.w);
            fma2(acc[0][0], a0, b01.x); fma2(acc[0][1], a0, b01.y);
            fma2(acc[0][2], a0, b23.x); fma2(acc[0][3], a0, b23.y);
            fma2(acc[1][0], a1, b01.x); fma2(acc[1][1], a1, b01.y);
            fma2(acc[1][2], a1, b23.x); fma2(acc[1][3], a1, b23.y);
            fma2(acc[2][0], a2, b01.x); fma2(acc[2][1], a2, b01.y);
            fma2(acc[2][2], a2, b23.x); fma2(acc[2][3], a2, b23.y);
            fma2(acc[3][0], a3, b01.x); fma2(acc[3][1], a3, b01.y);
            fma2(acc[3][2], a3, b23.x); fma2(acc[3][3], a3, b23.y);
        }
        if (kt + 1 < NT) {
            int nb = buf ^ 1;
            As[nb][acol + 0][arow] = pa.x;
            As[nb][acol + 1][arow] = pa.y;
            As[nb][acol + 2][arow] = pa.z;
            As[nb][acol + 3][arow] = pa.w;
            *(float4*)&Bs[nb][brow][bcol]     = pb0;
            *(float4*)&Bs[nb][brow + 8][bcol] = pb1;
            __syncthreads();
        }
    }

    int col0 = bn + tx * 8;
#pragma unroll
    for (int i = 0; i < 4; i++) {
        int r = bm + ty * 4 + i;
        float v[8];
        up2(acc[i][0], v[0], v[1]);
        up2(acc[i][1], v[2], v[3]);
        up2(acc[i][2], v[4], v[5]);
        up2(acc[i][3], v[6], v[7]);
        if (rowtab) {
            const float* tr = rowtab + (sym ? (size_t)sym[r] * (4 * HH) : 0) + col0;
#pragma unroll
            for (int j = 0; j < 8; j++) v[j] += tr[j];
        }
        if (bias) {
#pragma unroll
            for (int j = 0; j < 8; j++) v[j] += bias[col0 + j];
        }
        if (fuse) {
            // permuted cols: quadruple (i,f,g,o) for hidden unit jj
#pragma unroll
            for (int q = 0; q < 2; q++) {
                int jj = (col0 >> 2) + q;
                float ig = v[q * 4 + 0], fg = v[q * 4 + 1];
                float gg = v[q * 4 + 2], og = v[q * 4 + 3];
                size_t idx = (size_t)r * HH + jj;
                float cc = g_c[idx];
                float cn = sigmoidf_(fg) * cc + sigmoidf_(ig) * tanhf(gg);
                g_c[idx] = cn;
                hout[idx] = sigmoidf_(og) * tanhf(cn);
            }
        } else {
            float* Crow = C + (size_t)r * N + col0;
            *(float4*)Crow       = make_float4(v[0], v[1], v[2], v[3]);
            *(float4*)(Crow + 4) = make_float4(v[4], v[5], v[6], v[7]);
        }
    }
}

// ---------------------------------------------------------------------------
// Permute w_ih / w_hh columns (gate-major -> interleaved quadruples), fold bias
// ---------------------------------------------------------------------------
__global__ void __launch_bounds__(256)
permute_kernel(const float* __restrict__ wih, const float* __restrict__ whh,
               const float* __restrict__ bih, const float* __restrict__ bhh)
{
    int idx = blockIdx.x * 256 + threadIdx.x;       // 0 .. 512*2048-1
    int k = idx >> 11;
    int c = idx & 2047;
    int cp = ((c & 511) << 2) | (c >> 9);
    g_wih_perm[(size_t)k * 2048 + cp] = wih[idx];
    g_whh_perm[(size_t)k * 2048 + cp] = whh[idx];
    if (k == 0) g_bias_perm[cp] = bih[c] + bhh[c];
}

// sos row (uses permuted wih + bias; run after permute_kernel)
__global__ void __launch_bounds__(256)
sosrow_kernel(const float* __restrict__ sos)
{
    int cp = blockIdx.x * 256 + threadIdx.x;        // 0..2047
    float s = g_bias_perm[cp];
    for (int k = 0; k < EE; k++)
        s = fmaf(sos[k], g_wih_perm[(size_t)k * 2048 + cp], s);
    g_sosrow[cp] = s;
}

// zero c0
__global__ void __launch_bounds__(256)
initc_kernel()
{
    int idx = blockIdx.x * 256 + threadIdx.x;
    if (idx < BB * HH) g_c[idx] = 0.f;
}

// ---------------------------------------------------------------------------
// Per-row: log_softmax, probs, entropy, Gumbel-argmax sample (RNG inline)
// ---------------------------------------------------------------------------
__device__ __forceinline__ float neg_log_u(unsigned bits)
{
    float f = __uint_as_float(0x3f800000u | (bits >> 9));
    float u = f - 1.0f;
    if (u > 0.9f) {
        float d = 2.0f - f;
        return d * (1.0f + d * (0.5f + d * (0.333333343f + d * (0.25f +
               d * (0.2f + d * (0.166666672f + d * 0.142857149f))))));
    }
    if (u == 0.0f) u = 1.17549435e-38f;
    return -logf(u);
}

__global__ void __launch_bounds__(256)
sample_kernel(float* __restrict__ out, int t, unsigned sk0, unsigned sk1)
{
    const int T = 256;
    int b = blockIdx.x;
    int tid = threadIdx.x;
    __shared__ float s_row[VV];
    __shared__ float s_red[T];
    __shared__ int   s_idx[T];
    __shared__ float s_shift;

    const float* row = g_logits + (size_t)b * VV;
    const float NEG_INF = __int_as_float(0xff800000);

    // pass 1: load + max
    float m = NEG_INF;
    for (int v = tid; v < VV; v += T) {
        float x = row[v];
        s_row[v] = x;
        m = fmaxf(m, x);
    }
    s_red[tid] = m;
    __syncthreads();
    for (int o = T / 2; o > 0; o >>= 1) {
        if (tid < o) s_red[tid] = fmaxf(s_red[tid], s_red[tid + o]);
        __syncthreads();
    }
    m = s_red[0];
    __syncthreads();

    // pass 2: sum exp
    float z = 0.f;
    for (int v = tid; v < VV; v += T) z += expf(s_row[v] - m);
    s_red[tid] = z;
    __syncthreads();
    for (int o = T / 2; o > 0; o >>= 1) {
        if (tid < o) s_red[tid] += s_red[tid + o];
        __syncthreads();
    }
    if (tid == 0) s_shift = m + logf(s_red[0]);
    __syncthreads();
    float shift = s_shift;

    // pass 3: probs + entropy + gumbel + per-thread argmax
    float entsum = 0.f;
    float best = NEG_INF;
    int bi = 0;
    size_t pbase = PROB_OFF + ((size_t)b * (LL + 1) + t) * VV;
    for (int v = tid; v < VV; v += T) {
        float lp = s_row[v] - shift;
        float p = expf(lp);
        entsum += p * lp;
        out[pbase + v] = p;
        unsigned r0, r1;
        threefry2x32(sk0, sk1, 0u, (unsigned)(b * VV + v), r0, r1);
        unsigned bits = r0 ^ r1;
        float inner = neg_log_u(bits);
        float g = -logf(inner);
        float val = lp + g;
        if (val > best) { best = val; bi = v; }
    }

    // reduce entropy
    __syncthreads();
    s_red[tid] = entsum;
    __syncthreads();
    for (int o = T / 2; o > 0; o >>= 1) {
        if (tid < o) s_red[tid] += s_red[tid + o];
        __syncthreads();
    }
    float entv = -s_red[0];
    __syncthreads();

    // reduce argmax (tie -> lower index)
    s_red[tid] = best;
    s_idx[tid] = bi;
    __syncthreads();
    for (int o = T / 2; o > 0; o >>= 1) {
        if (tid < o) {
            float v2 = s_red[tid + o];
            int i2 = s_idx[tid + o];
            if (v2 > s_red[tid] || (v2 == s_red[tid] && i2 < s_idx[tid])) {
                s_red[tid] = v2;
                s_idx[tid] = i2;
            }
        }
        __syncthreads();
    }
    if (tid == 0) {
        int sym = s_idx[0];
        g_sym[b] = sym;
        size_t so = (size_t)b * (LL + 1) + t;
        out[SEQ_OFF + so]  = (float)sym;
        out[LOGP_OFF + so] = s_row[sym] - shift;
        out[ENT_OFF + so]  = entv;
    }
}

// ---------------------------------------------------------------------------
// EOS step (t = 32): seq/logp/ent = 0, probs = 1
// ---------------------------------------------------------------------------
__global__ void __launch_bounds__(256)
eos_kernel(float* __restrict__ out)
{
    int idx = blockIdx.x * blockDim.x + threadIdx.x;
    if (idx < BB * VV) {
        int b = idx / VV;
        int v = idx % VV;
        out[PROB_OFF + ((size_t)b * (LL + 1) + LL) * VV + v] = 1.0f;
    }
    if (idx < BB) {
        size_t so = (size_t)idx * (LL + 1) + LL;
        out[SEQ_OFF + so]  = 0.f;
        out[LOGP_OFF + so] = 0.f;
        out[ENT_OFF + so]  = 0.f;
    }
}

// ---------------------------------------------------------------------------
// Host launcher
// ---------------------------------------------------------------------------
extern "C" void kernel_launch(void* const* d_in, const int* in_sizes, int n_in,
                              void* d_out, int out_size)
{
    const float* x         = (const float*)d_in[0];
    const float* agent_w   = (const float*)d_in[1];
    const float* agent_b   = (const float*)d_in[2];
    const float* sos       = (const float*)d_in[3];
    const float* embedding = (const float*)d_in[4];
    const float* w_ih      = (const float*)d_in[5];
    const float* w_hh      = (const float*)d_in[6];
    const float* b_ih      = (const float*)d_in[7];
    const float* b_hh      = (const float*)d_in[8];
    const float* out_w     = (const float*)d_in[9];
    const float* out_b     = (const float*)d_in[10];
    float* out = (float*)d_out;

    float *h0p, *h1p, *lp, *tabp, *whhp, *sosp;
    int* symp;
    cudaGetSymbolAddress((void**)&h0p,  g_h0);
    cudaGetSymbolAddress((void**)&h1p,  g_h1);
    cudaGetSymbolAddress((void**)&lp,   g_logits);
    cudaGetSymbolAddress((void**)&tabp, g_table);
    cudaGetSymbolAddress((void**)&whhp, g_whh_perm);
    cudaGetSymbolAddress((void**)&sosp, g_sosrow);
    cudaGetSymbolAddress((void**)&symp, g_sym);
    float* wihp; cudaGetSymbolAddress((void**)&wihp, g_wih_perm);
    float* biasp; cudaGetSymbolAddress((void**)&biasp, g_bias_perm);

    float* hbuf[2] = { h0p, h1p };

    // Precompute: permuted weights, sos row, zero c, table, h0
    permute_kernel<<<(EE * 4 * HH) / 256, 256>>>(w_ih, w_hh, b_ih, b_hh);
    sosrow_kernel<<<(4 * HH) / 256, 256>>>(sos);
    initc_kernel<<<(BB * HH) / 256, 256>>>();
    // table = embedding @ wih_perm + bias_perm   [2048, 2048], K=512
    gemm_f2<<<dim3((4 * HH) / 128, VV / 64), 256>>>(
        embedding, wihp, EE, 4 * HH, biasp, nullptr, nullptr, tabp, nullptr, 0);
    // h0 = x @ agent_w + agent_b   [512, 512], K=1024
    gemm_f2<<<dim3(HH / 128, BB / 64), 256>>>(
        x, agent_w, IN_DIM, HH, agent_b, nullptr, nullptr, hbuf[0], nullptr, 0);

    // key chain: jax.random.key(1) -> (0, 1), partitionable threefry
    unsigned k0 = 0u, k1 = 1u;
    for (int t = 0; t < LL; t++) {
        unsigned nk0, nk1, sk0, sk1;
        threefry2x32(k0, k1, 0u, 0u, nk0, nk1);
        threefry2x32(k0, k1, 0u, 1u, sk0, sk1);
        k0 = nk0; k1 = nk1;

        const float* hA = hbuf[t & 1];
        float* hB = hbuf[(t + 1) & 1];

        // gates = hA @ whh_perm + rowtab  -> fused LSTM cell -> hB, g_c
        gemm_f2<<<dim3((4 * HH) / 128, BB / 64), 256>>>(
            hA, whhp, HH, 4 * HH, nullptr,
            (t == 0) ? sosp : tabp, (t == 0) ? nullptr : symp,
            nullptr, hB, 1);
        // logits = hB @ out_w + out_b   [512, 2048], K=512
        gemm_f2<<<dim3(VV / 128, BB / 64), 256>>>(
            hB, out_w, HH, VV, out_b, nullptr, nullptr, lp, nullptr, 0);
        // softmax + sample + outputs + sym
        sample_kernel<<<BB, 256>>>(out, t, sk0, sk1);
    }

    eos_kernel<<<(BB * VV + 255) / 256, 256>>>(out);
}

// round 8
// speedup vs baseline: 1.7797x; 1.1329x over previous
#include <cuda_runtime.h>
#include <cuda_bf16.h>
#include <math.h>
#include <stdint.h>

// Problem dims
#define BB 512
#define IN_DIM 1024
#define HH 512
#define EE 512
#define VV 2048
#define LL 32

// Output layout (floats): seq [512,33], probs [512,33,2048], logp [512,33], ent [512,33]
#define SEQ_OFF   ((size_t)0)
#define PROB_OFF  ((size_t)(BB * (LL + 1)))
#define LOGP_OFF  (PROB_OFF + (size_t)BB * (LL + 1) * VV)
#define ENT_OFF   (LOGP_OFF + (size_t)BB * (LL + 1))

// Scratch (device globals; no allocation allowed)
__device__ float g_h0[BB * HH];
__device__ float g_h1[BB * HH];
__device__ float g_c[BB * HH];
__device__ float g_logits[BB * VV];
__device__ float g_table[VV * 4 * HH];      // emb @ w_ih + b_ih + b_hh, permuted cols (16 MB)
__device__ float g_wih_perm[EE * 4 * HH];
__device__ float g_whh_perm[HH * 4 * HH];
__device__ float g_bias_perm[4 * HH];
__device__ float g_sosrow[4 * HH];          // sos @ w_ih + biases, permuted
__device__ int   g_sym[BB];

typedef unsigned long long ull;

// ---------------------------------------------------------------------------
// f32x2 helpers (sm_103a packed fp32 FMA)
// ---------------------------------------------------------------------------
__device__ __forceinline__ ull pk2(float x) {
    ull r; asm("mov.b64 %0,{%1,%1};" : "=l"(r) : "f"(x)); return r;
}
__device__ __forceinline__ void fma2(ull& d, ull a, ull b) {
    asm("fma.rn.f32x2 %0,%1,%2,%0;" : "+l"(d) : "l"(a), "l"(b));
}
__device__ __forceinline__ void up2(ull v, float& lo, float& hi) {
    asm("mov.b64 {%0,%1},%2;" : "=f"(lo), "=f"(hi) : "l"(v));
}

// ---------------------------------------------------------------------------
// Threefry2x32 (20 rounds) — device + host identical
// ---------------------------------------------------------------------------
__host__ __device__ __forceinline__ void threefry2x32(
    unsigned k0, unsigned k1, unsigned x0, unsigned x1,
    unsigned& o0, unsigned& o1)
{
    unsigned k2 = k0 ^ k1 ^ 0x1BD11BDAu;
    x0 += k0; x1 += k1;
#define TF_RND(r) { x0 += x1; x1 = (x1 << (r)) | (x1 >> (32 - (r))); x1 ^= x0; }
    TF_RND(13) TF_RND(15) TF_RND(26) TF_RND(6)   x0 += k1; x1 += k2 + 1u;
    TF_RND(17) TF_RND(29) TF_RND(16) TF_RND(24)  x0 += k2; x1 += k0 + 2u;
    TF_RND(13) TF_RND(15) TF_RND(26) TF_RND(6)   x0 += k0; x1 += k1 + 3u;
    TF_RND(17) TF_RND(29) TF_RND(16) TF_RND(24)  x0 += k1; x1 += k2 + 4u;
    TF_RND(13) TF_RND(15) TF_RND(26) TF_RND(6)   x0 += k2; x1 += k0 + 5u;
#undef TF_RND
    o0 = x0; o1 = x1;
}

__device__ __forceinline__ float sigmoidf_(float x) { return 1.f / (1.f + expf(-x)); }

// ---------------------------------------------------------------------------
// f32x2 SGEMM, BM=64 BN=128 BK=16, 128 threads, 8x8 per-thread tile.
// A stored transposed in smem -> accumulators pair ROWS: acc = {C[2i][j],C[2i+1][j]}
// A operand loads come out of smem already f32x2-packed (no dup movs on A).
// C[M,N] = A[M,K] @ W[K,N]  (+bias)  (+rowtab[sym[r]] or broadcast rowtab)
// fuse=1: permuted-gate LSTM epilogue -> writes hout, updates g_c (no C write)
// ---------------------------------------------------------------------------
__global__ void __launch_bounds__(128)
gemm_f2(const float* __restrict__ A, const float* __restrict__ W,
        int K, int N,
        const float* __restrict__ bias,
        const float* __restrict__ rowtab, const int* __restrict__ sym,
        float* __restrict__ C, float* __restrict__ hout, int fuse)
{
    __shared__ __align__(16) float As[2][16][64];   // [k][m] transposed
    __shared__ __align__(16) float Bs[2][16][128];

    int tid = threadIdx.x;
    int tx = tid & 15;         // 0..15 -> col group of 8
    int ty = tid >> 4;         // 0..7  -> row group of 8
    int bm = blockIdx.y * 64;
    int bn = blockIdx.x * 128;

    ull acc[4][8];             // acc[i2][j] = {C[ty*8+2*i2][c0+j], C[ty*8+2*i2+1][c0+j]}
#pragma unroll
    for (int i = 0; i < 4; i++)
#pragma unroll
        for (int j = 0; j < 8; j++) acc[i][j] = 0ull;

    // A load map: row = tid>>1 (0..63), col0 = (tid&1)*8 ; two float4
    int ar = tid >> 1;
    int ac = (tid & 1) << 3;
    // B load map: row = tid>>3 (0..15), col0 = (tid&7)*16 ; four float4
    int br = tid >> 3;
    int bc = (tid & 7) << 4;

    const float* Aptr = A + (size_t)(bm + ar) * K + ac;
    const float* Wptr = W + (size_t)br * N + bn + bc;
    int NT = K >> 4;

    float4 pa0, pa1, pb0, pb1, pb2, pb3;
    // preload tile 0
    pa0 = *(const float4*)Aptr;
    pa1 = *(const float4*)(Aptr + 4);
    pb0 = *(const float4*)Wptr;
    pb1 = *(const float4*)(Wptr + 4);
    pb2 = *(const float4*)(Wptr + 8);
    pb3 = *(const float4*)(Wptr + 12);
    {
        float av[8] = {pa0.x,pa0.y,pa0.z,pa0.w,pa1.x,pa1.y,pa1.z,pa1.w};
#pragma unroll
        for (int i = 0; i < 8; i++) As[0][ac + i][ar] = av[i];
        *(float4*)&Bs[0][br][bc]      = pb0;
        *(float4*)&Bs[0][br][bc + 4]  = pb1;
        *(float4*)&Bs[0][br][bc + 8]  = pb2;
        *(float4*)&Bs[0][br][bc + 12] = pb3;
    }
    __syncthreads();

    for (int kt = 0; kt < NT; kt++) {
        int buf = kt & 1;
        if (kt + 1 < NT) {
            const float* An = Aptr + (kt + 1) * 16;
            const float* Wn = Wptr + (size_t)(kt + 1) * 16 * N;
            pa0 = *(const float4*)An;
            pa1 = *(const float4*)(An + 4);
            pb0 = *(const float4*)Wn;
            pb1 = *(const float4*)(Wn + 4);
            pb2 = *(const float4*)(Wn + 8);
            pb3 = *(const float4*)(Wn + 12);
        }
#pragma unroll
        for (int kk = 0; kk < 16; kk++) {
            // A: two LDS.128 give four packed row-pairs
            ulonglong2 a01 = *(const ulonglong2*)&As[buf][kk][ty * 8];
            ulonglong2 a23 = *(const ulonglong2*)&As[buf][kk][ty * 8 + 4];
            // B: two LDS.128, duplicate each col scalar
            float4 b0 = *(const float4*)&Bs[buf][kk][tx * 8];
            float4 b1 = *(const float4*)&Bs[buf][kk][tx * 8 + 4];
            ull bb0 = pk2(b0.x), bb1 = pk2(b0.y), bb2 = pk2(b0.z), bb3 = pk2(b0.w);
            ull bb4 = pk2(b1.x), bb5 = pk2(b1.y), bb6 = pk2(b1.z), bb7 = pk2(b1.w);
            fma2(acc[0][0], a01.x, bb0); fma2(acc[0][1], a01.x, bb1);
            fma2(acc[0][2], a01.x, bb2); fma2(acc[0][3], a01.x, bb3);
            fma2(acc[0][4], a01.x, bb4); fma2(acc[0][5], a01.x, bb5);
            fma2(acc[0][6], a01.x, bb6); fma2(acc[0][7], a01.x, bb7);
            fma2(acc[1][0], a01.y, bb0); fma2(acc[1][1], a01.y, bb1);
            fma2(acc[1][2], a01.y, bb2); fma2(acc[1][3], a01.y, bb3);
            fma2(acc[1][4], a01.y, bb4); fma2(acc[1][5], a01.y, bb5);
            fma2(acc[1][6], a01.y, bb6); fma2(acc[1][7], a01.y, bb7);
            fma2(acc[2][0], a23.x, bb0); fma2(acc[2][1], a23.x, bb1);
            fma2(acc[2][2], a23.x, bb2); fma2(acc[2][3], a23.x, bb3);
            fma2(acc[2][4], a23.x, bb4); fma2(acc[2][5], a23.x, bb5);
            fma2(acc[2][6], a23.x, bb6); fma2(acc[2][7], a23.x, bb7);
            fma2(acc[3][0], a23.y, bb0); fma2(acc[3][1], a23.y, bb1);
            fma2(acc[3][2], a23.y, bb2); fma2(acc[3][3], a23.y, bb3);
            fma2(acc[3][4], a23.y, bb4); fma2(acc[3][5], a23.y, bb5);
            fma2(acc[3][6], a23.y, bb6); fma2(acc[3][7], a23.y, bb7);
        }
        if (kt + 1 < NT) {
            int nb = buf ^ 1;
            float av[8] = {pa0.x,pa0.y,pa0.z,pa0.w,pa1.x,pa1.y,pa1.z,pa1.w};
            __syncthreads();   // all reads of buf done before overwriting nb? nb != buf, but
                               // needed: reads of nb's OLD data finished last iter; ensure
                               // current-tile compute done before its buffer reuse next time.
#pragma unroll
            for (int i = 0; i < 8; i++) As[nb][ac + i][ar] = av[i];
            *(float4*)&Bs[nb][br][bc]      = pb0;
            *(float4*)&Bs[nb][br][bc + 4]  = pb1;
            *(float4*)&Bs[nb][br][bc + 8]  = pb2;
            *(float4*)&Bs[nb][br][bc + 12] = pb3;
            __syncthreads();
        }
    }

    int col0 = bn + tx * 8;
#pragma unroll
    for (int i2 = 0; i2 < 4; i2++) {
        float vlo[8], vhi[8];
#pragma unroll
        for (int j = 0; j < 8; j++) up2(acc[i2][j], vlo[j], vhi[j]);
#pragma unroll
        for (int half = 0; half < 2; half++) {
            float* v = half ? vhi : vlo;
            int r = bm + ty * 8 + 2 * i2 + half;
            if (rowtab) {
                const float* tr = rowtab + (sym ? (size_t)sym[r] * (4 * HH) : 0) + col0;
#pragma unroll
                for (int j = 0; j < 8; j++) v[j] += tr[j];
            }
            if (bias) {
#pragma unroll
                for (int j = 0; j < 8; j++) v[j] += bias[col0 + j];
            }
            if (fuse) {
                // permuted cols: quadruple (i,f,g,o) per hidden unit
#pragma unroll
                for (int q = 0; q < 2; q++) {
                    int jj = (col0 >> 2) + q;
                    float ig = v[q * 4 + 0], fg = v[q * 4 + 1];
                    float gg = v[q * 4 + 2], og = v[q * 4 + 3];
                    size_t idx = (size_t)r * HH + jj;
                    float cc = g_c[idx];
                    float cn = sigmoidf_(fg) * cc + sigmoidf_(ig) * tanhf(gg);
                    g_c[idx] = cn;
                    hout[idx] = sigmoidf_(og) * tanhf(cn);
                }
            } else {
                float* Crow = C + (size_t)r * N + col0;
                *(float4*)Crow       = make_float4(v[0], v[1], v[2], v[3]);
                *(float4*)(Crow + 4) = make_float4(v[4], v[5], v[6], v[7]);
            }
        }
    }
}

// ---------------------------------------------------------------------------
// Permute w_ih / w_hh columns (gate-major -> interleaved quadruples), fold bias
// ---------------------------------------------------------------------------
__global__ void __launch_bounds__(256)
permute_kernel(const float* __restrict__ wih, const float* __restrict__ whh,
               const float* __restrict__ bih, const float* __restrict__ bhh)
{
    int idx = blockIdx.x * 256 + threadIdx.x;       // 0 .. 512*2048-1
    int k = idx >> 11;
    int c = idx & 2047;
    int cp = ((c & 511) << 2) | (c >> 9);
    g_wih_perm[(size_t)k * 2048 + cp] = wih[idx];
    g_whh_perm[(size_t)k * 2048 + cp] = whh[idx];
    if (k == 0) g_bias_perm[cp] = bih[c] + bhh[c];
}

// sos row (uses permuted wih + bias; run after permute_kernel)
__global__ void __launch_bounds__(256)
sosrow_kernel(const float* __restrict__ sos)
{
    int cp = blockIdx.x * 256 + threadIdx.x;        // 0..2047
    float s = g_bias_perm[cp];
    for (int k = 0; k < EE; k++)
        s = fmaf(sos[k], g_wih_perm[(size_t)k * 2048 + cp], s);
    g_sosrow[cp] = s;
}

// zero c0
__global__ void __launch_bounds__(256)
initc_kernel()
{
    int idx = blockIdx.x * 256 + threadIdx.x;
    if (idx < BB * HH) g_c[idx] = 0.f;
}

// ---------------------------------------------------------------------------
// Per-row: log_softmax, probs, entropy, Gumbel-argmax sample (RNG inline)
// ---------------------------------------------------------------------------
__device__ __forceinline__ float neg_log_u(unsigned bits)
{
    float f = __uint_as_float(0x3f800000u | (bits >> 9));
    float u = f - 1.0f;
    if (u > 0.9f) {
        float d = 2.0f - f;
        return d * (1.0f + d * (0.5f + d * (0.333333343f + d * (0.25f +
               d * (0.2f + d * (0.166666672f + d * 0.142857149f))))));
    }
    if (u == 0.0f) u = 1.17549435e-38f;
    return -logf(u);
}

__global__ void __launch_bounds__(256)
sample_kernel(float* __restrict__ out, int t, unsigned sk0, unsigned sk1)
{
    const int T = 256;
    int b = blockIdx.x;
    int tid = threadIdx.x;
    __shared__ float s_row[VV];
    __shared__ float s_red[T];
    __shared__ int   s_idx[T];
    __shared__ float s_shift;

    const float* row = g_logits + (size_t)b * VV;
    const float NEG_INF = __int_as_float(0xff800000);

    // pass 1: load + max
    float m = NEG_INF;
    for (int v = tid; v < VV; v += T) {
        float x = row[v];
        s_row[v] = x;
        m = fmaxf(m, x);
    }
    s_red[tid] = m;
    __syncthreads();
    for (int o = T / 2; o > 0; o >>= 1) {
        if (tid < o) s_red[tid] = fmaxf(s_red[tid], s_red[tid + o]);
        __syncthreads();
    }
    m = s_red[0];
    __syncthreads();

    // pass 2: sum exp
    float z = 0.f;
    for (int v = tid; v < VV; v += T) z += expf(s_row[v] - m);
    s_red[tid] = z;
    __syncthreads();
    for (int o = T / 2; o > 0; o >>= 1) {
        if (tid < o) s_red[tid] += s_red[tid + o];
        __syncthreads();
    }
    if (tid == 0) s_shift = m + logf(s_red[0]);
    __syncthreads();
    float shift = s_shift;

    // pass 3: probs + entropy + gumbel + per-thread argmax
    float entsum = 0.f;
    float best = NEG_INF;
    int bi = 0;
    size_t pbase = PROB_OFF + ((size_t)b * (LL + 1) + t) * VV;
    for (int v = tid; v < VV; v += T) {
        float lp = s_row[v] - shift;
        float p = expf(lp);
        entsum += p * lp;
        out[pbase + v] = p;
        unsigned r0, r1;
        threefry2x32(sk0, sk1, 0u, (unsigned)(b * VV + v), r0, r1);
        unsigned bits = r0 ^ r1;
        float inner = neg_log_u(bits);
        float g = -logf(inner);
        float val = lp + g;
        if (val > best) { best = val; bi = v; }
    }

    // reduce entropy
    __syncthreads();
    s_red[tid] = entsum;
    __syncthreads();
    for (int o = T / 2; o > 0; o >>= 1) {
        if (tid < o) s_red[tid] += s_red[tid + o];
        __syncthreads();
    }
    float entv = -s_red[0];
    __syncthreads();

    // reduce argmax (tie -> lower index)
    s_red[tid] = best;
    s_idx[tid] = bi;
    __syncthreads();
    for (int o = T / 2; o > 0; o >>= 1) {
        if (tid < o) {
            float v2 = s_red[tid + o];
            int i2 = s_idx[tid + o];
            if (v2 > s_red[tid] || (v2 == s_red[tid] && i2 < s_idx[tid])) {
                s_red[tid] = v2;
                s_idx[tid] = i2;
            }
        }
        __syncthreads();
    }
    if (tid == 0) {
        int sym = s_idx[0];
        g_sym[b] = sym;
        size_t so = (size_t)b * (LL + 1) + t;
        out[SEQ_OFF + so]  = (float)sym;
        out[LOGP_OFF + so] = s_row[sym] - shift;
        out[ENT_OFF + so]  = entv;
    }
}

// ---------------------------------------------------------------------------
// EOS step (t = 32): seq/logp/ent = 0, probs = 1
// ---------------------------------------------------------------------------
__global__ void __launch_bounds__(256)
eos_kernel(float* __restrict__ out)
{
    int idx = blockIdx.x * blockDim.x + threadIdx.x;
    if (idx < BB * VV) {
        int b = idx / VV;
        int v = idx % VV;
        out[PROB_OFF + ((size_t)b * (LL + 1) + LL) * VV + v] = 1.0f;
    }
    if (idx < BB) {
        size_t so = (size_t)idx * (LL + 1) + LL;
        out[SEQ_OFF + so]  = 0.f;
        out[LOGP_OFF + so] = 0.f;
        out[ENT_OFF + so]  = 0.f;
    }
}

// ---------------------------------------------------------------------------
// Host launcher
// ---------------------------------------------------------------------------
extern "C" void kernel_launch(void* const* d_in, const int* in_sizes, int n_in,
                              void* d_out, int out_size)
{
    const float* x         = (const float*)d_in[0];
    const float* agent_w   = (const float*)d_in[1];
    const float* agent_b   = (const float*)d_in[2];
    const float* sos       = (const float*)d_in[3];
    const float* embedding = (const float*)d_in[4];
    const float* w_ih      = (const float*)d_in[5];
    const float* w_hh      = (const float*)d_in[6];
    const float* b_ih      = (const float*)d_in[7];
    const float* b_hh      = (const float*)d_in[8];
    const float* out_w     = (const float*)d_in[9];
    const float* out_b     = (const float*)d_in[10];
    float* out = (float*)d_out;

    float *h0p, *h1p, *lp, *tabp, *whhp, *sosp;
    int* symp;
    cudaGetSymbolAddress((void**)&h0p,  g_h0);
    cudaGetSymbolAddress((void**)&h1p,  g_h1);
    cudaGetSymbolAddress((void**)&lp,   g_logits);
    cudaGetSymbolAddress((void**)&tabp, g_table);
    cudaGetSymbolAddress((void**)&whhp, g_whh_perm);
    cudaGetSymbolAddress((void**)&sosp, g_sosrow);
    cudaGetSymbolAddress((void**)&symp, g_sym);
    float* wihp; cudaGetSymbolAddress((void**)&wihp, g_wih_perm);
    float* biasp; cudaGetSymbolAddress((void**)&biasp, g_bias_perm);

    float* hbuf[2] = { h0p, h1p };

    // Precompute: permuted weights, sos row, zero c, table, h0
    permute_kernel<<<(EE * 4 * HH) / 256, 256>>>(w_ih, w_hh, b_ih, b_hh);
    sosrow_kernel<<<(4 * HH) / 256, 256>>>(sos);
    initc_kernel<<<(BB * HH) / 256, 256>>>();
    // table = embedding @ wih_perm + bias_perm   [2048, 2048], K=512
    gemm_f2<<<dim3((4 * HH) / 128, VV / 64), 128>>>(
        embedding, wihp, EE, 4 * HH, biasp, nullptr, nullptr, tabp, nullptr, 0);
    // h0 = x @ agent_w + agent_b   [512, 512], K=1024
    gemm_f2<<<dim3(HH / 128, BB / 64), 128>>>(
        x, agent_w, IN_DIM, HH, agent_b, nullptr, nullptr, hbuf[0], nullptr, 0);

    // key chain: jax.random.key(1) -> (0, 1), partitionable threefry
    unsigned k0 = 0u, k1 = 1u;
    for (int t = 0; t < LL; t++) {
        unsigned nk0, nk1, sk0, sk1;
        threefry2x32(k0, k1, 0u, 0u, nk0, nk1);
        threefry2x32(k0, k1, 0u, 1u, sk0, sk1);
        k0 = nk0; k1 = nk1;

        const float* hA = hbuf[t & 1];
        float* hB = hbuf[(t + 1) & 1];

        // gates = hA @ whh_perm + rowtab  -> fused LSTM cell -> hB, g_c
        gemm_f2<<<dim3((4 * HH) / 128, BB / 64), 128>>>(
            hA, whhp, HH, 4 * HH, nullptr,
            (t == 0) ? sosp : tabp, (t == 0) ? nullptr : symp,
            nullptr, hB, 1);
        // logits = hB @ out_w + out_b   [512, 2048], K=512
        gemm_f2<<<dim3(VV / 128, BB / 64), 128>>>(
            hB, out_w, HH, VV, out_b, nullptr, nullptr, lp, nullptr, 0);
        // softmax + sample + outputs + sym
        sample_kernel<<<BB, 256>>>(out, t, sk0, sk1);
    }

    eos_kernel<<<(BB * VV + 255) / 256, 256>>>(out);
}

// round 9
// speedup vs baseline: 1.8911x; 1.0626x over previous
#include <cuda_runtime.h>
#include <cuda_bf16.h>
#include <math.h>
#include <stdint.h>

// Problem dims
#define BB 512
#define IN_DIM 1024
#define HH 512
#define EE 512
#define VV 2048
#define LL 32

// Output layout (floats): seq [512,33], probs [512,33,2048], logp [512,33], ent [512,33]
#define SEQ_OFF   ((size_t)0)
#define PROB_OFF  ((size_t)(BB * (LL + 1)))
#define LOGP_OFF  (PROB_OFF + (size_t)BB * (LL + 1) * VV)
#define ENT_OFF   (LOGP_OFF + (size_t)BB * (LL + 1))

// Scratch (device globals; no allocation allowed)
__device__ float g_h0[BB * HH];
__device__ float g_h1[BB * HH];
__device__ float g_c[BB * HH];
__device__ float g_logits[BB * VV];
__device__ float g_table[VV * 4 * HH];      // emb @ w_ih + b_ih + b_hh, permuted cols (16 MB)
__device__ float g_wih_perm[EE * 4 * HH];
__device__ float g_whh_perm[HH * 4 * HH];
__device__ float g_bias_perm[4 * HH];
__device__ float g_sosrow[4 * HH];          // sos @ w_ih + biases, permuted
__device__ int   g_sym[BB];

typedef unsigned long long ull;

// ---------------------------------------------------------------------------
// f32x2 helpers (sm_103a packed fp32 FMA)
// ---------------------------------------------------------------------------
__device__ __forceinline__ ull pk2(float x) {
    ull r; asm("mov.b64 %0,{%1,%1};" : "=l"(r) : "f"(x)); return r;
}
__device__ __forceinline__ void fma2(ull& d, ull a, ull b) {
    asm("fma.rn.f32x2 %0,%1,%2,%0;" : "+l"(d) : "l"(a), "l"(b));
}
__device__ __forceinline__ void add2(ull& d, ull a) {
    asm("add.rn.f32x2 %0,%0,%1;" : "+l"(d) : "l"(a));
}
__device__ __forceinline__ void up2(ull v, float& lo, float& hi) {
    asm("mov.b64 {%0,%1},%2;" : "=f"(lo), "=f"(hi) : "l"(v));
}

// ---------------------------------------------------------------------------
// Threefry2x32 (20 rounds) — device + host identical
// ---------------------------------------------------------------------------
__host__ __device__ __forceinline__ void threefry2x32(
    unsigned k0, unsigned k1, unsigned x0, unsigned x1,
    unsigned& o0, unsigned& o1)
{
    unsigned k2 = k0 ^ k1 ^ 0x1BD11BDAu;
    x0 += k0; x1 += k1;
#define TF_RND(r) { x0 += x1; x1 = (x1 << (r)) | (x1 >> (32 - (r))); x1 ^= x0; }
    TF_RND(13) TF_RND(15) TF_RND(26) TF_RND(6)   x0 += k1; x1 += k2 + 1u;
    TF_RND(17) TF_RND(29) TF_RND(16) TF_RND(24)  x0 += k2; x1 += k0 + 2u;
    TF_RND(13) TF_RND(15) TF_RND(26) TF_RND(6)   x0 += k0; x1 += k1 + 3u;
    TF_RND(17) TF_RND(29) TF_RND(16) TF_RND(24)  x0 += k1; x1 += k2 + 4u;
    TF_RND(13) TF_RND(15) TF_RND(26) TF_RND(6)   x0 += k2; x1 += k0 + 5u;
#undef TF_RND
    o0 = x0; o1 = x1;
}

__device__ __forceinline__ float sigmoidf_(float x) { return 1.f / (1.f + expf(-x)); }

// ---------------------------------------------------------------------------
// f32x2 SGEMM, BM=64 BN=128 BK=16, 256 threads (split-K-in-block: 2 halves of
// 128 threads each own 8 of the 16 kk slices and a full 8x8 f32x2 acc tile;
// halves are merged through a 32KB smem reduction overlaid on the tile bufs).
// As stored transposed [k][m] so A operand loads are naturally f32x2 row-pairs.
// C[M,N] = A[M,K] @ W[K,N]  (+bias)  (+rowtab[sym[r]] or broadcast rowtab)
// fuse=1: permuted-gate LSTM epilogue -> writes hout, updates g_c (no C write)
// ---------------------------------------------------------------------------
__global__ void __launch_bounds__(256)
gemm_f2(const float* __restrict__ A, const float* __restrict__ W,
        int K, int N,
        const float* __restrict__ bias,
        const float* __restrict__ rowtab, const int* __restrict__ sym,
        float* __restrict__ C, float* __restrict__ hout, int fuse)
{
    // 32KB shared: [0,8K) As[2][16][64], [8K,24K) Bs[2][16][128]; reused as
    // 32KB ull reduction buffer after the mainloop.
    __shared__ __align__(16) char s_mem[32768];
    float (*As)[16][64]  = (float (*)[16][64])s_mem;
    float (*Bs)[16][128] = (float (*)[16][128])(s_mem + 8192);
    ull* red = (ull*)s_mem;

    int tid  = threadIdx.x;
    int half = tid >> 7;        // 0 or 1: kk-half
    int htid = tid & 127;
    int tx = htid & 15;         // 0..15 -> col group of 8
    int ty = htid >> 4;         // 0..7  -> row group of 8
    int bm = blockIdx.y * 64;
    int bn = blockIdx.x * 128;
    int kk0 = half << 3;        // 0 or 8

    ull acc[4][8];              // acc[i2][j] = {C[ty*8+2*i2][c0+j], C[..+1][c0+j]}
#pragma unroll
    for (int i = 0; i < 4; i++)
#pragma unroll
        for (int j = 0; j < 8; j++) acc[i][j] = 0ull;

    // A load: 64x16 floats = 256 float4, one per thread
    int ar = tid >> 2;              // 0..63
    int ac = (tid & 3) << 2;        // 0,4,8,12
    // B load: 16x128 floats = 512 float4, two per thread
    int br = tid >> 4;              // 0..15
    int bc = (tid & 15) << 3;       // 0..120

    const float* Aptr = A + (size_t)(bm + ar) * K + ac;
    const float* Wptr = W + (size_t)br * N + bn + bc;
    int NT = K >> 4;

    float4 pa, pb0, pb1;
    // preload tile 0
    pa  = *(const float4*)Aptr;
    pb0 = *(const float4*)Wptr;
    pb1 = *(const float4*)(Wptr + 4);
    As[0][ac + 0][ar] = pa.x;
    As[0][ac + 1][ar] = pa.y;
    As[0][ac + 2][ar] = pa.z;
    As[0][ac + 3][ar] = pa.w;
    *(float4*)&Bs[0][br][bc]     = pb0;
    *(float4*)&Bs[0][br][bc + 4] = pb1;
    __syncthreads();

    for (int kt = 0; kt < NT; kt++) {
        int buf = kt & 1;
        if (kt + 1 < NT) {
            const float* An = Aptr + (kt + 1) * 16;
            const float* Wn = Wptr + (size_t)(kt + 1) * 16 * N;
            pa  = *(const float4*)An;
            pb0 = *(const float4*)Wn;
            pb1 = *(const float4*)(Wn + 4);
        }
#pragma unroll
        for (int kk = 0; kk < 8; kk++) {
            int kx = kk0 + kk;
            // A: two LDS.128 give four packed row-pairs
            ulonglong2 a01 = *(const ulonglong2*)&As[buf][kx][ty * 8];
            ulonglong2 a23 = *(const ulonglong2*)&As[buf][kx][ty * 8 + 4];
            // B: two LDS.128, duplicate each col scalar (movs ride the idle alu pipe)
            float4 b0 = *(const float4*)&Bs[buf][kx][tx * 8];
            float4 b1 = *(const float4*)&Bs[buf][kx][tx * 8 + 4];
            ull bb0 = pk2(b0.x), bb1 = pk2(b0.y), bb2 = pk2(b0.z), bb3 = pk2(b0.w);
            ull bb4 = pk2(b1.x), bb5 = pk2(b1.y), bb6 = pk2(b1.z), bb7 = pk2(b1.w);
            fma2(acc[0][0], a01.x, bb0); fma2(acc[0][1], a01.x, bb1);
            fma2(acc[0][2], a01.x, bb2); fma2(acc[0][3], a01.x, bb3);
            fma2(acc[0][4], a01.x, bb4); fma2(acc[0][5], a01.x, bb5);
            fma2(acc[0][6], a01.x, bb6); fma2(acc[0][7], a01.x, bb7);
            fma2(acc[1][0], a01.y, bb0); fma2(acc[1][1], a01.y, bb1);
            fma2(acc[1][2], a01.y, bb2); fma2(acc[1][3], a01.y, bb3);
            fma2(acc[1][4], a01.y, bb4); fma2(acc[1][5], a01.y, bb5);
            fma2(acc[1][6], a01.y, bb6); fma2(acc[1][7], a01.y, bb7);
            fma2(acc[2][0], a23.x, bb0); fma2(acc[2][1], a23.x, bb1);
            fma2(acc[2][2], a23.x, bb2); fma2(acc[2][3], a23.x, bb3);
            fma2(acc[2][4], a23.x, bb4); fma2(acc[2][5], a23.x, bb5);
            fma2(acc[2][6], a23.x, bb6); fma2(acc[2][7], a23.x, bb7);
            fma2(acc[3][0], a23.y, bb0); fma2(acc[3][1], a23.y, bb1);
            fma2(acc[3][2], a23.y, bb2); fma2(acc[3][3], a23.y, bb3);
            fma2(acc[3][4], a23.y, bb4); fma2(acc[3][5], a23.y, bb5);
            fma2(acc[3][6], a23.y, bb6); fma2(acc[3][7], a23.y, bb7);
        }
        if (kt + 1 < NT) {
            int nb = buf ^ 1;
            __syncthreads();
            As[nb][ac + 0][ar] = pa.x;
            As[nb][ac + 1][ar] = pa.y;
            As[nb][ac + 2][ar] = pa.z;
            As[nb][ac + 3][ar] = pa.w;
            *(float4*)&Bs[nb][br][bc]     = pb0;
            *(float4*)&Bs[nb][br][bc + 4] = pb1;
            __syncthreads();
        }
    }

    // merge halves: half 1 spills accs, half 0 adds (idx-major layout: conflict-free)
    __syncthreads();
    if (half == 1) {
#pragma unroll
        for (int i = 0; i < 4; i++)
#pragma unroll
            for (int j = 0; j < 8; j++)
                red[(i * 8 + j) * 128 + htid] = acc[i][j];
    }
    __syncthreads();
    if (half == 0) {
#pragma unroll
        for (int i = 0; i < 4; i++)
#pragma unroll
            for (int j = 0; j < 8; j++)
                add2(acc[i][j], red[(i * 8 + j) * 128 + htid]);

        int col0 = bn + tx * 8;
#pragma unroll
        for (int i2 = 0; i2 < 4; i2++) {
            float vlo[8], vhi[8];
#pragma unroll
            for (int j = 0; j < 8; j++) up2(acc[i2][j], vlo[j], vhi[j]);
#pragma unroll
            for (int hf = 0; hf < 2; hf++) {
                float* v = hf ? vhi : vlo;
                int r = bm + ty * 8 + 2 * i2 + hf;
                if (rowtab) {
                    const float* tr = rowtab + (sym ? (size_t)sym[r] * (4 * HH) : 0) + col0;
#pragma unroll
                    for (int j = 0; j < 8; j++) v[j] += tr[j];
                }
                if (bias) {
#pragma unroll
                    for (int j = 0; j < 8; j++) v[j] += bias[col0 + j];
                }
                if (fuse) {
                    // permuted cols: quadruple (i,f,g,o) per hidden unit
#pragma unroll
                    for (int q = 0; q < 2; q++) {
                        int jj = (col0 >> 2) + q;
                        float ig = v[q * 4 + 0], fg = v[q * 4 + 1];
                        float gg = v[q * 4 + 2], og = v[q * 4 + 3];
                        size_t idx = (size_t)r * HH + jj;
                        float cc = g_c[idx];
                        float cn = sigmoidf_(fg) * cc + sigmoidf_(ig) * tanhf(gg);
                        g_c[idx] = cn;
                        hout[idx] = sigmoidf_(og) * tanhf(cn);
                    }
                } else {
                    float* Crow = C + (size_t)r * N + col0;
                    *(float4*)Crow       = make_float4(v[0], v[1], v[2], v[3]);
                    *(float4*)(Crow + 4) = make_float4(v[4], v[5], v[6], v[7]);
                }
            }
        }
    }
}

// ---------------------------------------------------------------------------
// Permute w_ih / w_hh columns (gate-major -> interleaved quadruples), fold bias
// ---------------------------------------------------------------------------
__global__ void __launch_bounds__(256)
permute_kernel(const float* __restrict__ wih, const float* __restrict__ whh,
               const float* __restrict__ bih, const float* __restrict__ bhh)
{
    int idx = blockIdx.x * 256 + threadIdx.x;       // 0 .. 512*2048-1
    int k = idx >> 11;
    int c = idx & 2047;
    int cp = ((c & 511) << 2) | (c >> 9);
    g_wih_perm[(size_t)k * 2048 + cp] = wih[idx];
    g_whh_perm[(size_t)k * 2048 + cp] = whh[idx];
    if (k == 0) g_bias_perm[cp] = bih[c] + bhh[c];
}

// sos row (uses permuted wih + bias; run after permute_kernel)
__global__ void __launch_bounds__(256)
sosrow_kernel(const float* __restrict__ sos)
{
    int cp = blockIdx.x * 256 + threadIdx.x;        // 0..2047
    float s = g_bias_perm[cp];
    for (int k = 0; k < EE; k++)
        s = fmaf(sos[k], g_wih_perm[(size_t)k * 2048 + cp], s);
    g_sosrow[cp] = s;
}

// zero c0
__global__ void __launch_bounds__(256)
initc_kernel()
{
    int idx = blockIdx.x * 256 + threadIdx.x;
    if (idx < BB * HH) g_c[idx] = 0.f;
}

// ---------------------------------------------------------------------------
// Per-row: log_softmax, probs, entropy, Gumbel-argmax sample (RNG inline)
// ---------------------------------------------------------------------------
__device__ __forceinline__ float neg_log_u(unsigned bits)
{
    float f = __uint_as_float(0x3f800000u | (bits >> 9));
    float u = f - 1.0f;
    if (u > 0.9f) {
        float d = 2.0f - f;
        return d * (1.0f + d * (0.5f + d * (0.333333343f + d * (0.25f +
               d * (0.2f + d * (0.166666672f + d * 0.142857149f))))));
    }
    if (u == 0.0f) u = 1.17549435e-38f;
    return -logf(u);
}

__global__ void __launch_bounds__(256)
sample_kernel(float* __restrict__ out, int t, unsigned sk0, unsigned sk1)
{
    const int T = 256;
    int b = blockIdx.x;
    int tid = threadIdx.x;
    __shared__ float s_row[VV];
    __shared__ float s_red[T];
    __shared__ int   s_idx[T];
    __shared__ float s_shift;

    const float* row = g_logits + (size_t)b * VV;
    const float NEG_INF = __int_as_float(0xff800000);

    // pass 1: load + max
    float m = NEG_INF;
    for (int v = tid; v < VV; v += T) {
        float x = row[v];
        s_row[v] = x;
        m = fmaxf(m, x);
    }
    s_red[tid] = m;
    __syncthreads();
    for (int o = T / 2; o > 0; o >>= 1) {
        if (tid < o) s_red[tid] = fmaxf(s_red[tid], s_red[tid + o]);
        __syncthreads();
    }
    m = s_red[0];
    __syncthreads();

    // pass 2: sum exp
    float z = 0.f;
    for (int v = tid; v < VV; v += T) z += expf(s_row[v] - m);
    s_red[tid] = z;
    __syncthreads();
    for (int o = T / 2; o > 0; o >>= 1) {
        if (tid < o) s_red[tid] += s_red[tid + o];
        __syncthreads();
    }
    if (tid == 0) s_shift = m + logf(s_red[0]);
    __syncthreads();
    float shift = s_shift;

    // pass 3: probs + entropy + gumbel + per-thread argmax
    float entsum = 0.f;
    float best = NEG_INF;
    int bi = 0;
    size_t pbase = PROB_OFF + ((size_t)b * (LL + 1) + t) * VV;
    for (int v = tid; v < VV; v += T) {
        float lp = s_row[v] - shift;
        float p = expf(lp);
        entsum += p * lp;
        out[pbase + v] = p;
        unsigned r0, r1;
        threefry2x32(sk0, sk1, 0u, (unsigned)(b * VV + v), r0, r1);
        unsigned bits = r0 ^ r1;
        float inner = neg_log_u(bits);
        float g = -logf(inner);
        float val = lp + g;
        if (val > best) { best = val; bi = v; }
    }

    // reduce entropy
    __syncthreads();
    s_red[tid] = entsum;
    __syncthreads();
    for (int o = T / 2; o > 0; o >>= 1) {
        if (tid < o) s_red[tid] += s_red[tid + o];
        __syncthreads();
    }
    float entv = -s_red[0];
    __syncthreads();

    // reduce argmax (tie -> lower index)
    s_red[tid] = best;
    s_idx[tid] = bi;
    __syncthreads();
    for (int o = T / 2; o > 0; o >>= 1) {
        if (tid < o) {
            float v2 = s_red[tid + o];
            int i2 = s_idx[tid + o];
            if (v2 > s_red[tid] || (v2 == s_red[tid] && i2 < s_idx[tid])) {
                s_red[tid] = v2;
                s_idx[tid] = i2;
            }
        }
        __syncthreads();
    }
    if (tid == 0) {
        int sym = s_idx[0];
        g_sym[b] = sym;
        size_t so = (size_t)b * (LL + 1) + t;
        out[SEQ_OFF + so]  = (float)sym;
        out[LOGP_OFF + so] = s_row[sym] - shift;
        out[ENT_OFF + so]  = entv;
    }
}

// ---------------------------------------------------------------------------
// EOS step (t = 32): seq/logp/ent = 0, probs = 1
// ---------------------------------------------------------------------------
__global__ void __launch_bounds__(256)
eos_kernel(float* __restrict__ out)
{
    int idx = blockIdx.x * blockDim.x + threadIdx.x;
    if (idx < BB * VV) {
        int b = idx / VV;
        int v = idx % VV;
        out[PROB_OFF + ((size_t)b * (LL + 1) + LL) * VV + v] = 1.0f;
    }
    if (idx < BB) {
        size_t so = (size_t)idx * (LL + 1) + LL;
        out[SEQ_OFF + so]  = 0.f;
        out[LOGP_OFF + so] = 0.f;
        out[ENT_OFF + so]  = 0.f;
    }
}

// ---------------------------------------------------------------------------
// Host launcher
// ---------------------------------------------------------------------------
extern "C" void kernel_launch(void* const* d_in, const int* in_sizes, int n_in,
                              void* d_out, int out_size)
{
    const float* x         = (const float*)d_in[0];
    const float* agent_w   = (const float*)d_in[1];
    const float* agent_b   = (const float*)d_in[2];
    const float* sos       = (const float*)d_in[3];
    const float* embedding = (const float*)d_in[4];
    const float* w_ih      = (const float*)d_in[5];
    const float* w_hh      = (const float*)d_in[6];
    const float* b_ih      = (const float*)d_in[7];
    const float* b_hh      = (const float*)d_in[8];
    const float* out_w     = (const float*)d_in[9];
    const float* out_b     = (const float*)d_in[10];
    float* out = (float*)d_out;

    float *h0p, *h1p, *lp, *tabp, *whhp, *sosp;
    int* symp;
    cudaGetSymbolAddress((void**)&h0p,  g_h0);
    cudaGetSymbolAddress((void**)&h1p,  g_h1);
    cudaGetSymbolAddress((void**)&lp,   g_logits);
    cudaGetSymbolAddress((void**)&tabp, g_table);
    cudaGetSymbolAddress((void**)&whhp, g_whh_perm);
    cudaGetSymbolAddress((void**)&sosp, g_sosrow);
    cudaGetSymbolAddress((void**)&symp, g_sym);
    float* wihp; cudaGetSymbolAddress((void**)&wihp, g_wih_perm);
    float* biasp; cudaGetSymbolAddress((void**)&biasp, g_bias_perm);

    float* hbuf[2] = { h0p, h1p };

    // Precompute: permuted weights, sos row, zero c, table, h0
    permute_kernel<<<(EE * 4 * HH) / 256, 256>>>(w_ih, w_hh, b_ih, b_hh);
    sosrow_kernel<<<(4 * HH) / 256, 256>>>(sos);
    initc_kernel<<<(BB * HH) / 256, 256>>>();
    // table = embedding @ wih_perm + bias_perm   [2048, 2048], K=512
    gemm_f2<<<dim3((4 * HH) / 128, VV / 64), 256>>>(
        embedding, wihp, EE, 4 * HH, biasp, nullptr, nullptr, tabp, nullptr, 0);
    // h0 = x @ agent_w + agent_b   [512, 512], K=1024
    gemm_f2<<<dim3(HH / 128, BB / 64), 256>>>(
        x, agent_w, IN_DIM, HH, agent_b, nullptr, nullptr, hbuf[0], nullptr, 0);

    // key chain: jax.random.key(1) -> (0, 1), partitionable threefry
    unsigned k0 = 0u, k1 = 1u;
    for (int t = 0; t < LL; t++) {
        unsigned nk0, nk1, sk0, sk1;
        threefry2x32(k0, k1, 0u, 0u, nk0, nk1);
        threefry2x32(k0, k1, 0u, 1u, sk0, sk1);
        k0 = nk0; k1 = nk1;

        const float* hA = hbuf[t & 1];
        float* hB = hbuf[(t + 1) & 1];

        // gates = hA @ whh_perm + rowtab  -> fused LSTM cell -> hB, g_c
        gemm_f2<<<dim3((4 * HH) / 128, BB / 64), 256>>>(
            hA, whhp, HH, 4 * HH, nullptr,
            (t == 0) ? sosp : tabp, (t == 0) ? nullptr : symp,
            nullptr, hB, 1);
        // logits = hB @ out_w + out_b   [512, 2048], K=512
        gemm_f2<<<dim3(VV / 128, BB / 64), 256>>>(
            hB, out_w, HH, VV, out_b, nullptr, nullptr, lp, nullptr, 0);
        // softmax + sample + outputs + sym
        sample_kernel<<<BB, 256>>>(out, t, sk0, sk1);
    }

    eos_kernel<<<(BB * VV + 255) / 256, 256>>>(out);
}